// round 1
// baseline (speedup 1.0000x reference)
#include <cuda_runtime.h>

#define B_ 4
#define S_ 4096
#define D_ 128
#define NROWS (B_*S_)
#define BQ 32
#define BK 64

// Scratch (device globals: allocation-free per harness rules)
__device__ float g_Q[NROWS*D_];
__device__ float g_K[NROWS*D_];
__device__ float g_V[NROWS*D_];

typedef unsigned long long u64;

// ---- packed fp32x2 helpers (FFMA2 path: full-rate fp32 on sm_10x) ----
__device__ __forceinline__ u64 bcast2(float v) {
    u64 r; asm("mov.b64 %0, {%1, %1};" : "=l"(r) : "f"(v)); return r;
}
__device__ __forceinline__ void unpack2(u64 v, float &lo, float &hi) {
    asm("mov.b64 {%0, %1}, %2;" : "=f"(lo), "=f"(hi) : "l"(v));
}
__device__ __forceinline__ void fma2(u64 &d, u64 a, u64 b) {
    asm("fma.rn.f32x2 %0, %1, %2, %0;" : "+l"(d) : "l"(a), "l"(b));
}
__device__ __forceinline__ void mul2(u64 &d, u64 a) {
    asm("mul.rn.f32x2 %0, %0, %1;" : "+l"(d) : "l"(a));
}

// ============================================================
// Kernel 1: QKV projection. grid = (NROWS/64, 3), 256 threads.
// Tile: 64 rows x 128 cols, thread = 4 rows x 8 cols (4 f32x2 pairs).
// ============================================================
__global__ __launch_bounds__(256) void proj_kernel(
    const float* __restrict__ emb, const float* __restrict__ WQ,
    const float* __restrict__ WK,  const float* __restrict__ WV)
{
    extern __shared__ float sm[];
    float* Ws = sm;            // [128][128]
    float* Es = sm + D_*D_;    // [64][128]
    const float* W   = blockIdx.y == 0 ? WQ  : (blockIdx.y == 1 ? WK  : WV);
    float*       dst = blockIdx.y == 0 ? g_Q : (blockIdx.y == 1 ? g_K : g_V);
    const int row0 = blockIdx.x * 64;
    const int tid  = threadIdx.x;

    for (int i = tid; i < D_*D_/4; i += 256)
        ((float4*)Ws)[i] = ((const float4*)W)[i];
    const float4* eg = (const float4*)(emb + (size_t)row0 * D_);
    for (int i = tid; i < 64*D_/4; i += 256)
        ((float4*)Es)[i] = eg[i];
    __syncthreads();

    const int tx = tid & 15, ty = tid >> 4;
    u64 acc[4][4];
#pragma unroll
    for (int r = 0; r < 4; r++)
#pragma unroll
        for (int c = 0; c < 4; c++) acc[r][c] = 0ull;

#pragma unroll 4
    for (int k = 0; k < D_; k++) {
        const ulonglong2 w0 = *(const ulonglong2*)&Ws[k*D_ + tx*8];
        const ulonglong2 w1 = *(const ulonglong2*)&Ws[k*D_ + tx*8 + 4];
#pragma unroll
        for (int r = 0; r < 4; r++) {
            u64 e = bcast2(Es[(ty*4 + r)*D_ + k]);   // broadcast LDS
            fma2(acc[r][0], w0.x, e);
            fma2(acc[r][1], w0.y, e);
            fma2(acc[r][2], w1.x, e);
            fma2(acc[r][3], w1.y, e);
        }
    }
#pragma unroll
    for (int r = 0; r < 4; r++) {
        float o[8];
        unpack2(acc[r][0], o[0], o[1]); unpack2(acc[r][1], o[2], o[3]);
        unpack2(acc[r][2], o[4], o[5]); unpack2(acc[r][3], o[6], o[7]);
        float* p = dst + (size_t)(row0 + ty*4 + r)*D_ + tx*8;
        *(float4*)p       = make_float4(o[0], o[1], o[2], o[3]);
        *(float4*)(p + 4) = make_float4(o[4], o[5], o[6], o[7]);
    }
}

// ============================================================
// Kernel 2: causal flash attention. grid = (S/BQ, B), 256 threads.
// Thread = 2 q-rows x (4 score cols | 8 out cols). Row group = 16 lanes (tx).
// Q,K stored transposed in smem -> broadcast/conflict-free score loop.
// ============================================================
__global__ __launch_bounds__(256) void attn_kernel(float* __restrict__ out)
{
    extern __shared__ float sm[];
    float* Qt = sm;                 // [128][32]  (d-major, scaled)
    float* Kt = Qt + D_*BQ;         // [128][64]  (d-major)
    float* Vs = Kt + D_*BK;         // [64][128]
    float* Ps = Vs + BK*D_;         // [32][64]

    const int b  = blockIdx.y;
    const int qt = (int)gridDim.x - 1 - (int)blockIdx.x;  // heavy tiles first
    const int q0 = qt * BQ;
    const float* Qg = g_Q + ((size_t)b*S_ + q0) * D_;
    const float* Kg = g_K + (size_t)b*S_*D_;
    const float* Vg = g_V + (size_t)b*S_*D_;
    const int tid = threadIdx.x;
    const int tx  = tid & 15, ty = tid >> 4;
    const float scale = 0.08838834764831845f;   // 1/sqrt(128), folded into Q

    // Load Q transposed & pre-scaled (smem stores conflict-free: i contiguous)
    for (int idx = tid; idx < (D_/4)*BQ; idx += 256) {
        int i = idx & (BQ - 1), d4 = idx / BQ;
        float4 q = *(const float4*)&Qg[(size_t)i*D_ + d4*4];
        Qt[(d4*4 + 0)*BQ + i] = q.x * scale;
        Qt[(d4*4 + 1)*BQ + i] = q.y * scale;
        Qt[(d4*4 + 2)*BQ + i] = q.z * scale;
        Qt[(d4*4 + 3)*BQ + i] = q.w * scale;
    }

    float m0 = -1e30f, m1 = -1e30f, l0 = 0.f, l1 = 0.f;
    u64 O0[4], O1[4];
#pragma unroll
    for (int c = 0; c < 4; c++) { O0[c] = 0ull; O1[c] = 0ull; }

    const int nkt = (q0 >> 6) + 1;   // tiles with k0 <= q0+31; only last needs mask
    for (int kt = 0; kt < nkt; kt++) {
        const int k0 = kt * BK;
        __syncthreads();  // previous PV done before overwriting K/V
        for (int idx = tid; idx < (D_/4)*BK; idx += 256) {
            int j = idx & (BK - 1), d4 = idx / BK;
            float4 k = *(const float4*)&Kg[(size_t)(k0 + j)*D_ + d4*4];
            Kt[(d4*4 + 0)*BK + j] = k.x;
            Kt[(d4*4 + 1)*BK + j] = k.y;
            Kt[(d4*4 + 2)*BK + j] = k.z;
            Kt[(d4*4 + 3)*BK + j] = k.w;
        }
        for (int idx = tid; idx < BK*(D_/4); idx += 256) {
            int d4 = idx & (D_/4 - 1), j = idx >> 5;
            *(float4*)&Vs[j*D_ + d4*4] = *(const float4*)&Vg[(size_t)(k0 + j)*D_ + d4*4];
        }
        __syncthreads();

        // ---- S = (Q*scale) K^T : packed f32x2, 8 MAC / 2 LDS per d ----
        u64 Sp00 = 0ull, Sp01 = 0ull, Sp10 = 0ull, Sp11 = 0ull;
#pragma unroll 4
        for (int d = 0; d < D_; d++) {
            float2     q  = *(const float2*)&Qt[d*BQ + ty*2];     // 2 rows, bcast
            ulonglong2 k2 = *(const ulonglong2*)&Kt[d*BK + tx*4]; // 4 cols as 2 pairs
            u64 qx = bcast2(q.x), qy = bcast2(q.y);
            fma2(Sp00, k2.x, qx); fma2(Sp01, k2.y, qx);
            fma2(Sp10, k2.x, qy); fma2(Sp11, k2.y, qy);
        }
        float s0[4], s1[4];
        unpack2(Sp00, s0[0], s0[1]); unpack2(Sp01, s0[2], s0[3]);
        unpack2(Sp10, s1[0], s1[1]); unpack2(Sp11, s1[2], s1[3]);

        if (kt == nkt - 1) {   // diagonal tile: mask j > i
            const int i0 = q0 + ty*2, jb = k0 + tx*4;
#pragma unroll
            for (int c = 0; c < 4; c++) {
                if (jb + c > i0)     s0[c] = -1e30f;
                if (jb + c > i0 + 1) s1[c] = -1e30f;
            }
        }

        // ---- online softmax (row = 16 consecutive lanes) ----
        float mt0 = fmaxf(fmaxf(s0[0], s0[1]), fmaxf(s0[2], s0[3]));
        float mt1 = fmaxf(fmaxf(s1[0], s1[1]), fmaxf(s1[2], s1[3]));
#pragma unroll
        for (int off = 8; off; off >>= 1) {
            mt0 = fmaxf(mt0, __shfl_xor_sync(0xffffffffu, mt0, off, 16));
            mt1 = fmaxf(mt1, __shfl_xor_sync(0xffffffffu, mt1, off, 16));
        }
        float mn0 = fmaxf(m0, mt0), mn1 = fmaxf(m1, mt1);
        float a0 = __expf(m0 - mn0), a1 = __expf(m1 - mn1);
        m0 = mn0; m1 = mn1;

        float p0[4], p1[4], ps0 = 0.f, ps1 = 0.f;
#pragma unroll
        for (int c = 0; c < 4; c++) {
            p0[c] = __expf(s0[c] - m0); ps0 += p0[c];
            p1[c] = __expf(s1[c] - m1); ps1 += p1[c];
        }
        *(float4*)&Ps[(ty*2 + 0)*BK + tx*4] = make_float4(p0[0], p0[1], p0[2], p0[3]);
        *(float4*)&Ps[(ty*2 + 1)*BK + tx*4] = make_float4(p1[0], p1[1], p1[2], p1[3]);
#pragma unroll
        for (int off = 8; off; off >>= 1) {
            ps0 += __shfl_xor_sync(0xffffffffu, ps0, off, 16);
            ps1 += __shfl_xor_sync(0xffffffffu, ps1, off, 16);
        }
        l0 = l0*a0 + ps0;  l1 = l1*a1 + ps1;
        u64 a0p = bcast2(a0), a1p = bcast2(a1);
#pragma unroll
        for (int c = 0; c < 4; c++) { mul2(O0[c], a0p); mul2(O1[c], a1p); }
        __syncthreads();  // Ps visible to whole row group

        // ---- O += P V : 16 MAC / 4 LDS per j ----
#pragma unroll 4
        for (int j = 0; j < BK; j++) {
            ulonglong2 v0 = *(const ulonglong2*)&Vs[j*D_ + tx*8];
            ulonglong2 v1 = *(const ulonglong2*)&Vs[j*D_ + tx*8 + 4];
            u64 pj0 = bcast2(Ps[(ty*2 + 0)*BK + j]);   // broadcast LDS
            u64 pj1 = bcast2(Ps[(ty*2 + 1)*BK + j]);
            fma2(O0[0], v0.x, pj0); fma2(O0[1], v0.y, pj0);
            fma2(O0[2], v1.x, pj0); fma2(O0[3], v1.y, pj0);
            fma2(O1[0], v0.x, pj1); fma2(O1[1], v0.y, pj1);
            fma2(O1[2], v1.x, pj1); fma2(O1[3], v1.y, pj1);
        }
    }

    // ---- epilogue: normalize + coalesced store ----
    u64 inv0 = bcast2(1.f / l0), inv1 = bcast2(1.f / l1);
#pragma unroll
    for (int c = 0; c < 4; c++) { mul2(O0[c], inv0); mul2(O1[c], inv1); }
    float o0[8], o1[8];
    unpack2(O0[0], o0[0], o0[1]); unpack2(O0[1], o0[2], o0[3]);
    unpack2(O0[2], o0[4], o0[5]); unpack2(O0[3], o0[6], o0[7]);
    unpack2(O1[0], o1[0], o1[1]); unpack2(O1[1], o1[2], o1[3]);
    unpack2(O1[2], o1[4], o1[5]); unpack2(O1[3], o1[6], o1[7]);
    float* d0 = out + ((size_t)b*S_ + q0 + ty*2 + 0)*D_ + tx*8;
    float* d1 = out + ((size_t)b*S_ + q0 + ty*2 + 1)*D_ + tx*8;
    *(float4*)d0       = make_float4(o0[0], o0[1], o0[2], o0[3]);
    *(float4*)(d0 + 4) = make_float4(o0[4], o0[5], o0[6], o0[7]);
    *(float4*)d1       = make_float4(o1[0], o1[1], o1[2], o1[3]);
    *(float4*)(d1 + 4) = make_float4(o1[4], o1[5], o1[6], o1[7]);
}

// ============================================================
extern "C" void kernel_launch(void* const* d_in, const int* in_sizes, int n_in,
                              void* d_out, int out_size)
{
    (void)in_sizes; (void)n_in; (void)out_size;
    const float* emb = (const float*)d_in[0];
    const float* WQ  = (const float*)d_in[1];
    const float* WK  = (const float*)d_in[2];
    const float* WV  = (const float*)d_in[3];
    float* out = (float*)d_out;

    const int smem_proj = (D_*D_ + 64*D_) * (int)sizeof(float);              // 96 KB
    const int smem_attn = (D_*BQ + D_*BK + BK*D_ + BQ*BK) * (int)sizeof(float); // 88 KB
    cudaFuncSetAttribute(proj_kernel, cudaFuncAttributeMaxDynamicSharedMemorySize, smem_proj);
    cudaFuncSetAttribute(attn_kernel, cudaFuncAttributeMaxDynamicSharedMemorySize, smem_attn);

    proj_kernel<<<dim3(NROWS/64, 3), 256, smem_proj>>>(emb, WQ, WK, WV);
    attn_kernel<<<dim3(S_/BQ, B_), 256, smem_attn>>>(out);
}

// round 2
// speedup vs baseline: 1.9391x; 1.9391x over previous
#include <cuda_runtime.h>

#define B_ 4
#define S_ 4096
#define D_ 128
#define NROWS (B_*S_)
#define BQ 64
#define BK 64
#define PSS 68   // padded P row stride (floats), 16B-aligned, conflict-mitigating

// Scratch (device globals: allocation-free per harness rules)
__device__ float g_Q[NROWS*D_];
__device__ float g_K[NROWS*D_];
__device__ float g_V[NROWS*D_];

typedef unsigned long long u64;

// ---- packed fp32x2 helpers (FFMA2 path: full-rate fp32 on sm_10x) ----
__device__ __forceinline__ u64 bcast2(float v) {
    u64 r; asm("mov.b64 %0, {%1, %1};" : "=l"(r) : "f"(v)); return r;
}
__device__ __forceinline__ void unpack2(u64 v, float &lo, float &hi) {
    asm("mov.b64 {%0, %1}, %2;" : "=f"(lo), "=f"(hi) : "l"(v));
}
__device__ __forceinline__ void fma2(u64 &d, u64 a, u64 b) {
    asm("fma.rn.f32x2 %0, %1, %2, %0;" : "+l"(d) : "l"(a), "l"(b));
}
__device__ __forceinline__ void mul2(u64 &d, u64 a) {
    asm("mul.rn.f32x2 %0, %0, %1;" : "+l"(d) : "l"(a));
}

// ============================================================
// Kernel 1: QKV projection. grid = (NROWS/64, 3), 256 threads.
// ============================================================
__global__ __launch_bounds__(256) void proj_kernel(
    const float* __restrict__ emb, const float* __restrict__ WQ,
    const float* __restrict__ WK,  const float* __restrict__ WV)
{
    extern __shared__ float sm[];
    float* Ws = sm;            // [128][128]
    float* Es = sm + D_*D_;    // [64][128]
    const float* W   = blockIdx.y == 0 ? WQ  : (blockIdx.y == 1 ? WK  : WV);
    float*       dst = blockIdx.y == 0 ? g_Q : (blockIdx.y == 1 ? g_K : g_V);
    const int row0 = blockIdx.x * 64;
    const int tid  = threadIdx.x;

    for (int i = tid; i < D_*D_/4; i += 256)
        ((float4*)Ws)[i] = ((const float4*)W)[i];
    const float4* eg = (const float4*)(emb + (size_t)row0 * D_);
    for (int i = tid; i < 64*D_/4; i += 256)
        ((float4*)Es)[i] = eg[i];
    __syncthreads();

    const int tx = tid & 15, ty = tid >> 4;
    u64 acc[4][4];
#pragma unroll
    for (int r = 0; r < 4; r++)
#pragma unroll
        for (int c = 0; c < 4; c++) acc[r][c] = 0ull;

#pragma unroll 4
    for (int k = 0; k < D_; k++) {
        const ulonglong2 w0 = *(const ulonglong2*)&Ws[k*D_ + tx*8];
        const ulonglong2 w1 = *(const ulonglong2*)&Ws[k*D_ + tx*8 + 4];
#pragma unroll
        for (int r = 0; r < 4; r++) {
            u64 e = bcast2(Es[(ty*4 + r)*D_ + k]);
            fma2(acc[r][0], w0.x, e);
            fma2(acc[r][1], w0.y, e);
            fma2(acc[r][2], w1.x, e);
            fma2(acc[r][3], w1.y, e);
        }
    }
#pragma unroll
    for (int r = 0; r < 4; r++) {
        float o[8];
        unpack2(acc[r][0], o[0], o[1]); unpack2(acc[r][1], o[2], o[3]);
        unpack2(acc[r][2], o[4], o[5]); unpack2(acc[r][3], o[6], o[7]);
        float* p = dst + (size_t)(row0 + ty*4 + r)*D_ + tx*8;
        *(float4*)p       = make_float4(o[0], o[1], o[2], o[3]);
        *(float4*)(p + 4) = make_float4(o[4], o[5], o[6], o[7]);
    }
}

// ============================================================
// Kernel 2: causal flash attention, pair-balanced.
// grid = (32, B), 256 threads. Block handles q-tiles (63-bx) and bx
// => every block does exactly 65 k-tiles. One wave, 1 CTA/SM.
// Thread tile: QK 4 rows x 4 cols; PV 4 rows x 8 d-cols (tx*4 and 64+tx*4).
// ============================================================
__global__ __launch_bounds__(256, 1) void attn_kernel(float* __restrict__ out)
{
    extern __shared__ float sm[];
    float* Qt = sm;                 // [128][64]  d-major, pre-scaled
    float* Kt = Qt + D_*BQ;         // [128][64]  d-major
    float* Vs = Kt + D_*BK;         // [64][128]
    float* Ps = Vs + BK*D_;         // [64][PSS]

    const int b   = blockIdx.y;
    const int tid = threadIdx.x;
    const int tx  = tid & 15, ty = tid >> 4;   // ty 0..15 -> 4 q-rows each
    const float scale = 0.08838834764831845f;  // 1/sqrt(128)

    const float* Kg = g_K + (size_t)b*S_*D_;
    const float* Vg = g_V + (size_t)b*S_*D_;

#pragma unroll 1
    for (int half = 0; half < 2; half++) {
        const int qt = half ? (int)blockIdx.x : 63 - (int)blockIdx.x; // heavy first
        const int q0 = qt * BQ;
        const float* Qg = g_Q + ((size_t)b*S_ + q0) * D_;

        __syncthreads();   // Qt safe to overwrite
        // Load Q transposed + pre-scaled (clean STS banks: j contiguous per warp)
        for (int idx = tid; idx < (D_/4)*BQ; idx += 256) {
            int i = idx & (BQ-1), d4 = idx >> 6;
            float4 q = *(const float4*)&Qg[(size_t)i*D_ + d4*4];
            Qt[(d4*4 + 0)*BQ + i] = q.x * scale;
            Qt[(d4*4 + 1)*BQ + i] = q.y * scale;
            Qt[(d4*4 + 2)*BQ + i] = q.z * scale;
            Qt[(d4*4 + 3)*BQ + i] = q.w * scale;
        }

        float m[4], l[4];
        u64 O[4][4];
#pragma unroll
        for (int r = 0; r < 4; r++) {
            m[r] = -1e30f; l[r] = 0.f;
#pragma unroll
            for (int c = 0; c < 4; c++) O[r][c] = 0ull;
        }

        const int nkt = qt + 1;
        for (int kt = 0; kt < nkt; kt++) {
            const int k0 = kt * BK;
            __syncthreads();   // prev tile's PV done before overwriting K/V
            // K transposed (strided LDG, conflict-free STS)
            for (int idx = tid; idx < (D_/4)*BK; idx += 256) {
                int j = idx & (BK-1), d4 = idx >> 6;
                float4 k = *(const float4*)&Kg[(size_t)(k0 + j)*D_ + d4*4];
                Kt[(d4*4 + 0)*BK + j] = k.x;
                Kt[(d4*4 + 1)*BK + j] = k.y;
                Kt[(d4*4 + 2)*BK + j] = k.z;
                Kt[(d4*4 + 3)*BK + j] = k.w;
            }
            // V direct (coalesced both sides)
            for (int idx = tid; idx < BK*(D_/4); idx += 256) {
                int d4 = idx & (D_/4 - 1), j = idx >> 5;
                *(float4*)&Vs[j*D_ + d4*4] =
                    *(const float4*)&Vg[(size_t)(k0 + j)*D_ + d4*4];
            }
            __syncthreads();

            // ---- S = Q K^T : 4x4 per thread, 8 FFMA2 per 3 wavefronts ----
            u64 acc[4][2];
#pragma unroll
            for (int r = 0; r < 4; r++) { acc[r][0] = 0ull; acc[r][1] = 0ull; }
#pragma unroll 4
            for (int d = 0; d < D_; d++) {
                float4     qv = *(const float4*)&Qt[d*BQ + ty*4];     // 2 addr/warp
                ulonglong2 kv = *(const ulonglong2*)&Kt[d*BK + tx*4]; // 256B contig
                u64 qb0 = bcast2(qv.x), qb1 = bcast2(qv.y);
                u64 qb2 = bcast2(qv.z), qb3 = bcast2(qv.w);
                fma2(acc[0][0], kv.x, qb0); fma2(acc[0][1], kv.y, qb0);
                fma2(acc[1][0], kv.x, qb1); fma2(acc[1][1], kv.y, qb1);
                fma2(acc[2][0], kv.x, qb2); fma2(acc[2][1], kv.y, qb2);
                fma2(acc[3][0], kv.x, qb3); fma2(acc[3][1], kv.y, qb3);
            }
            float s[4][4];
#pragma unroll
            for (int r = 0; r < 4; r++) {
                unpack2(acc[r][0], s[r][0], s[r][1]);
                unpack2(acc[r][1], s[r][2], s[r][3]);
            }

            if (kt == nkt - 1) {  // diagonal tile (k0 == q0): mask j > i
#pragma unroll
                for (int r = 0; r < 4; r++)
#pragma unroll
                    for (int c = 0; c < 4; c++)
                        if (tx*4 + c > ty*4 + r) s[r][c] = -1e30f;
            }

            // ---- online softmax, rows span 16 lanes (tx) ----
            float mt[4], a[4], p[4][4], ps[4];
#pragma unroll
            for (int r = 0; r < 4; r++)
                mt[r] = fmaxf(fmaxf(s[r][0], s[r][1]), fmaxf(s[r][2], s[r][3]));
#pragma unroll
            for (int off = 8; off; off >>= 1)
#pragma unroll
                for (int r = 0; r < 4; r++)
                    mt[r] = fmaxf(mt[r], __shfl_xor_sync(0xffffffffu, mt[r], off, 16));
#pragma unroll
            for (int r = 0; r < 4; r++) {
                float mn = fmaxf(m[r], mt[r]);
                a[r] = __expf(m[r] - mn);
                m[r] = mn;
                ps[r] = 0.f;
#pragma unroll
                for (int c = 0; c < 4; c++) { p[r][c] = __expf(s[r][c] - m[r]); ps[r] += p[r][c]; }
            }
#pragma unroll
            for (int off = 8; off; off >>= 1)
#pragma unroll
                for (int r = 0; r < 4; r++)
                    ps[r] += __shfl_xor_sync(0xffffffffu, ps[r], off, 16);
#pragma unroll
            for (int r = 0; r < 4; r++) {
                l[r] = l[r]*a[r] + ps[r];
                u64 ab = bcast2(a[r]);
#pragma unroll
                for (int c = 0; c < 4; c++) mul2(O[r][c], ab);
                *(float4*)&Ps[(ty*4 + r)*PSS + tx*4] =
                    make_float4(p[r][0], p[r][1], p[r][2], p[r][3]);
            }
            __syncwarp();   // P rows are warp-private: producer == consumer warp

            // ---- O += P V : p as float4 rows, V contiguous float4 pairs ----
#pragma unroll 2
            for (int j4 = 0; j4 < BK; j4 += 4) {
                float4 pr[4];
#pragma unroll
                for (int r = 0; r < 4; r++)
                    pr[r] = *(const float4*)&Ps[(ty*4 + r)*PSS + j4];
                const float* prf = (const float*)pr;
#pragma unroll
                for (int jj = 0; jj < 4; jj++) {
                    ulonglong2 v0 = *(const ulonglong2*)&Vs[(j4+jj)*D_ + tx*4];
                    ulonglong2 v1 = *(const ulonglong2*)&Vs[(j4+jj)*D_ + 64 + tx*4];
#pragma unroll
                    for (int r = 0; r < 4; r++) {
                        u64 pb = bcast2(prf[r*4 + jj]);
                        fma2(O[r][0], v0.x, pb); fma2(O[r][1], v0.y, pb);
                        fma2(O[r][2], v1.x, pb); fma2(O[r][3], v1.y, pb);
                    }
                }
            }
        }

        // ---- epilogue: normalize + store (cols tx*4 and 64+tx*4) ----
#pragma unroll
        for (int r = 0; r < 4; r++) {
            u64 inv = bcast2(1.f / l[r]);
#pragma unroll
            for (int c = 0; c < 4; c++) mul2(O[r][c], inv);
            float o[8];
            unpack2(O[r][0], o[0], o[1]); unpack2(O[r][1], o[2], o[3]);
            unpack2(O[r][2], o[4], o[5]); unpack2(O[r][3], o[6], o[7]);
            float* dp = out + ((size_t)b*S_ + q0 + ty*4 + r)*D_;
            *(float4*)(dp + tx*4)      = make_float4(o[0], o[1], o[2], o[3]);
            *(float4*)(dp + 64 + tx*4) = make_float4(o[4], o[5], o[6], o[7]);
        }
    }
}

// ============================================================
extern "C" void kernel_launch(void* const* d_in, const int* in_sizes, int n_in,
                              void* d_out, int out_size)
{
    (void)in_sizes; (void)n_in; (void)out_size;
    const float* emb = (const float*)d_in[0];
    const float* WQ  = (const float*)d_in[1];
    const float* WK  = (const float*)d_in[2];
    const float* WV  = (const float*)d_in[3];
    float* out = (float*)d_out;

    const int smem_proj = (D_*D_ + 64*D_) * (int)sizeof(float);   // 96 KB
    // Qt + Kt + Vs + Ps, padded past 113.5KB so 2 CTAs can never co-schedule
    const int smem_attn = (D_*BQ + D_*BK + BK*D_ + BQ*PSS + 160) * (int)sizeof(float);
    cudaFuncSetAttribute(proj_kernel, cudaFuncAttributeMaxDynamicSharedMemorySize, smem_proj);
    cudaFuncSetAttribute(attn_kernel, cudaFuncAttributeMaxDynamicSharedMemorySize, smem_attn);

    proj_kernel<<<dim3(NROWS/64, 3), 256, smem_proj>>>(emb, WQ, WK, WV);
    attn_kernel<<<dim3(32, B_), 256, smem_attn>>>(out);
}

// round 3
// speedup vs baseline: 2.1243x; 1.0955x over previous
#include <cuda_runtime.h>

#define B_ 4
#define S_ 4096
#define D_ 128
#define NROWS (B_*S_)
#define BQ 64
#define BK 128
#define PSS 132   // padded P row stride (floats)
#define NT 512

// Scratch (device globals: allocation-free per harness rules)
__device__ float g_Q[NROWS*D_];
__device__ float g_K[NROWS*D_];
__device__ float g_V[NROWS*D_];

typedef unsigned long long u64;

// ---- packed fp32x2 helpers (FFMA2 path: full-rate fp32 on sm_10x) ----
__device__ __forceinline__ u64 bcast2(float v) {
    u64 r; asm("mov.b64 %0, {%1, %1};" : "=l"(r) : "f"(v)); return r;
}
__device__ __forceinline__ void unpack2(u64 v, float &lo, float &hi) {
    asm("mov.b64 {%0, %1}, %2;" : "=f"(lo), "=f"(hi) : "l"(v));
}
__device__ __forceinline__ void fma2(u64 &d, u64 a, u64 b) {
    asm("fma.rn.f32x2 %0, %1, %2, %0;" : "+l"(d) : "l"(a), "l"(b));
}
__device__ __forceinline__ void mul2(u64 &d, u64 a) {
    asm("mul.rn.f32x2 %0, %0, %1;" : "+l"(d) : "l"(a));
}

// ============================================================
// Kernel 1: QKV projection. grid = (NROWS/64, 3), 256 threads.
// ============================================================
__global__ __launch_bounds__(256) void proj_kernel(
    const float* __restrict__ emb, const float* __restrict__ WQ,
    const float* __restrict__ WK,  const float* __restrict__ WV)
{
    extern __shared__ float sm[];
    float* Ws = sm;            // [128][128]
    float* Es = sm + D_*D_;    // [64][128]
    const float* W   = blockIdx.y == 0 ? WQ  : (blockIdx.y == 1 ? WK  : WV);
    float*       dst = blockIdx.y == 0 ? g_Q : (blockIdx.y == 1 ? g_K : g_V);
    const int row0 = blockIdx.x * 64;
    const int tid  = threadIdx.x;

    for (int i = tid; i < D_*D_/4; i += 256)
        ((float4*)Ws)[i] = ((const float4*)W)[i];
    const float4* eg = (const float4*)(emb + (size_t)row0 * D_);
    for (int i = tid; i < 64*D_/4; i += 256)
        ((float4*)Es)[i] = eg[i];
    __syncthreads();

    const int tx = tid & 15, ty = tid >> 4;
    u64 acc[4][4];
#pragma unroll
    for (int r = 0; r < 4; r++)
#pragma unroll
        for (int c = 0; c < 4; c++) acc[r][c] = 0ull;

#pragma unroll 4
    for (int k = 0; k < D_; k++) {
        const ulonglong2 w0 = *(const ulonglong2*)&Ws[k*D_ + tx*8];
        const ulonglong2 w1 = *(const ulonglong2*)&Ws[k*D_ + tx*8 + 4];
#pragma unroll
        for (int r = 0; r < 4; r++) {
            u64 e = bcast2(Es[(ty*4 + r)*D_ + k]);
            fma2(acc[r][0], w0.x, e);
            fma2(acc[r][1], w0.y, e);
            fma2(acc[r][2], w1.x, e);
            fma2(acc[r][3], w1.y, e);
        }
    }
#pragma unroll
    for (int r = 0; r < 4; r++) {
        float o[8];
        unpack2(acc[r][0], o[0], o[1]); unpack2(acc[r][1], o[2], o[3]);
        unpack2(acc[r][2], o[4], o[5]); unpack2(acc[r][3], o[6], o[7]);
        float* p = dst + (size_t)(row0 + ty*4 + r)*D_ + tx*8;
        *(float4*)p       = make_float4(o[0], o[1], o[2], o[3]);
        *(float4*)(p + 4) = make_float4(o[4], o[5], o[6], o[7]);
    }
}

// ============================================================
// Kernel 2: causal flash attention. grid = (32, B), 512 threads.
// Block pair-processes q-tiles (63-bx, bx): exactly 33 BK=128 k-tiles
// each => one balanced wave, 1 CTA/SM, 16 warps/SM.
// Warp = 2 q-row-groups x 16 k-col-groups (crossbar-friendly).
// Row reductions: shfl width-16 + cross-warp combine via smem.
// ============================================================
__global__ __launch_bounds__(NT, 1) void attn_kernel(float* __restrict__ out)
{
    extern __shared__ float sm[];
    float* Qt = sm;                   // [128][64]   d-major, pre-scaled
    float* Kt = Qt + D_*BQ;           // [128][128]  d-major
    float* Vs = Kt + D_*BK;           // [128][128]
    float* Ps = Vs + BK*D_;           // [64][PSS]
    float* Mp = Ps + BQ*PSS;          // [2][64] cross-warp max partials
    float* Lp = Mp + 2*BQ;            // [2][64] cross-warp sum partials

    const int b    = blockIdx.y;
    const int tid  = threadIdx.x;
    const int w    = tid >> 5;
    const int lane = tid & 31;
    const int tyb  = lane >> 4;            // 0..1
    const int txl  = lane & 15;            // 0..15
    const int ty   = ((w & 7) << 1) | tyb; // 0..15 -> 4 q-rows each
    const int half = w >> 3;               // 0..1
    const int tx   = txl | (half << 4);    // 0..31 -> 4 k-cols each
    const float scale = 0.08838834764831845f;  // 1/sqrt(128)

    const float* Kg = g_K + (size_t)b*S_*D_;
    const float* Vg = g_V + (size_t)b*S_*D_;

#pragma unroll 1
    for (int hf = 0; hf < 2; hf++) {
        const int qt = hf ? (int)blockIdx.x : 63 - (int)blockIdx.x; // heavy first
        const int q0 = qt * BQ;
        const float* Qg = g_Q + ((size_t)b*S_ + q0) * D_;

        __syncthreads();   // prev half's QK done -> Qt safe to overwrite
        for (int idx = tid; idx < (D_/4)*BQ; idx += NT) {
            int i = idx & (BQ-1), d4 = idx >> 6;
            float4 q = *(const float4*)&Qg[(size_t)i*D_ + d4*4];
            Qt[(d4*4 + 0)*BQ + i] = q.x * scale;
            Qt[(d4*4 + 1)*BQ + i] = q.y * scale;
            Qt[(d4*4 + 2)*BQ + i] = q.z * scale;
            Qt[(d4*4 + 3)*BQ + i] = q.w * scale;
        }

        float m[4], l[4];
        u64 O[4][2];
#pragma unroll
        for (int r = 0; r < 4; r++) {
            m[r] = -1e30f; l[r] = 0.f;
            O[r][0] = 0ull; O[r][1] = 0ull;
        }

        const int nkt = (qt >> 1) + 1;   // 128-wide k-tiles covering [0, q0+63]
        for (int kt = 0; kt < nkt; kt++) {
            const int k0 = kt * BK;
            __syncthreads();   // prev tile's PV done before overwriting K/V
            // K transposed into Kt[d][j]
            for (int idx = tid; idx < (D_/4)*BK; idx += NT) {
                int j = idx & (BK-1), d4 = idx >> 7;
                float4 k = *(const float4*)&Kg[(size_t)(k0 + j)*D_ + d4*4];
                Kt[(d4*4 + 0)*BK + j] = k.x;
                Kt[(d4*4 + 1)*BK + j] = k.y;
                Kt[(d4*4 + 2)*BK + j] = k.z;
                Kt[(d4*4 + 3)*BK + j] = k.w;
            }
            // V direct (coalesced)
            for (int idx = tid; idx < BK*(D_/4); idx += NT) {
                int d4 = idx & (D_/4 - 1), j = idx >> 5;
                *(float4*)&Vs[j*D_ + d4*4] =
                    *(const float4*)&Vg[(size_t)(k0 + j)*D_ + d4*4];
            }
            __syncthreads();

            // ---- S = Q K^T : 4x4 per thread ----
            u64 acc[4][2];
#pragma unroll
            for (int r = 0; r < 4; r++) { acc[r][0] = 0ull; acc[r][1] = 0ull; }
#pragma unroll 4
            for (int d = 0; d < D_; d++) {
                float4     qv = *(const float4*)&Qt[d*BQ + ty*4];     // 2 addr/warp
                ulonglong2 kv = *(const ulonglong2*)&Kt[d*BK + tx*4]; // 256B/warp
                u64 qb0 = bcast2(qv.x), qb1 = bcast2(qv.y);
                u64 qb2 = bcast2(qv.z), qb3 = bcast2(qv.w);
                fma2(acc[0][0], kv.x, qb0); fma2(acc[0][1], kv.y, qb0);
                fma2(acc[1][0], kv.x, qb1); fma2(acc[1][1], kv.y, qb1);
                fma2(acc[2][0], kv.x, qb2); fma2(acc[2][1], kv.y, qb2);
                fma2(acc[3][0], kv.x, qb3); fma2(acc[3][1], kv.y, qb3);
            }
            float s[4][4];
#pragma unroll
            for (int r = 0; r < 4; r++) {
                unpack2(acc[r][0], s[r][0], s[r][1]);
                unpack2(acc[r][1], s[r][2], s[r][3]);
            }

            if (kt == nkt - 1) {  // diagonal tile: mask global j > i
#pragma unroll
                for (int r = 0; r < 4; r++)
#pragma unroll
                    for (int c = 0; c < 4; c++)
                        if (k0 + tx*4 + c > q0 + ty*4 + r) s[r][c] = -1e30f;
            }

            // ---- row max: width-16 shfl + cross-warp smem combine ----
            float mt[4];
#pragma unroll
            for (int r = 0; r < 4; r++)
                mt[r] = fmaxf(fmaxf(s[r][0], s[r][1]), fmaxf(s[r][2], s[r][3]));
#pragma unroll
            for (int off = 8; off; off >>= 1)
#pragma unroll
                for (int r = 0; r < 4; r++)
                    mt[r] = fmaxf(mt[r], __shfl_xor_sync(0xffffffffu, mt[r], off, 16));
            if (txl == 0)
#pragma unroll
                for (int r = 0; r < 4; r++) Mp[half*BQ + ty*4 + r] = mt[r];
            __syncthreads();

            float a[4], p[4][4], ps[4];
#pragma unroll
            for (int r = 0; r < 4; r++) {
                float mn = fmaxf(m[r], fmaxf(Mp[ty*4 + r], Mp[BQ + ty*4 + r]));
                a[r] = __expf(m[r] - mn);
                m[r] = mn;
                ps[r] = 0.f;
#pragma unroll
                for (int c = 0; c < 4; c++) { p[r][c] = __expf(s[r][c] - mn); ps[r] += p[r][c]; }
                *(float4*)&Ps[(ty*4 + r)*PSS + tx*4] =
                    make_float4(p[r][0], p[r][1], p[r][2], p[r][3]);
            }
#pragma unroll
            for (int off = 8; off; off >>= 1)
#pragma unroll
                for (int r = 0; r < 4; r++)
                    ps[r] += __shfl_xor_sync(0xffffffffu, ps[r], off, 16);
            if (txl == 0)
#pragma unroll
                for (int r = 0; r < 4; r++) Lp[half*BQ + ty*4 + r] = ps[r];
            __syncthreads();   // Lp ready AND Ps fully visible for PV

#pragma unroll
            for (int r = 0; r < 4; r++) {
                l[r] = l[r]*a[r] + Lp[ty*4 + r] + Lp[BQ + ty*4 + r];
                u64 ab = bcast2(a[r]);
                mul2(O[r][0], ab); mul2(O[r][1], ab);
            }

            // ---- O += P V : thread covers 4 d-cols (tx*4) ----
#pragma unroll 2
            for (int j4 = 0; j4 < BK; j4 += 4) {
                float4 pr[4];
#pragma unroll
                for (int r = 0; r < 4; r++)
                    pr[r] = *(const float4*)&Ps[(ty*4 + r)*PSS + j4];
                const float* prf = (const float*)pr;
#pragma unroll
                for (int jj = 0; jj < 4; jj++) {
                    ulonglong2 v = *(const ulonglong2*)&Vs[(j4+jj)*D_ + tx*4];
#pragma unroll
                    for (int r = 0; r < 4; r++) {
                        u64 pb = bcast2(prf[r*4 + jj]);
                        fma2(O[r][0], v.x, pb); fma2(O[r][1], v.y, pb);
                    }
                }
            }
        }

        // ---- epilogue: normalize + store ----
#pragma unroll
        for (int r = 0; r < 4; r++) {
            u64 inv = bcast2(1.f / l[r]);
            mul2(O[r][0], inv); mul2(O[r][1], inv);
            float o[4];
            unpack2(O[r][0], o[0], o[1]); unpack2(O[r][1], o[2], o[3]);
            float* dp = out + ((size_t)b*S_ + q0 + ty*4 + r)*D_ + tx*4;
            *(float4*)dp = make_float4(o[0], o[1], o[2], o[3]);
        }
    }
}

// ============================================================
extern "C" void kernel_launch(void* const* d_in, const int* in_sizes, int n_in,
                              void* d_out, int out_size)
{
    (void)in_sizes; (void)n_in; (void)out_size;
    const float* emb = (const float*)d_in[0];
    const float* WQ  = (const float*)d_in[1];
    const float* WK  = (const float*)d_in[2];
    const float* WV  = (const float*)d_in[3];
    float* out = (float*)d_out;

    const int smem_proj = (D_*D_ + 64*D_) * (int)sizeof(float);   // 96 KB
    const int smem_attn = (D_*BQ + D_*BK + BK*D_ + BQ*PSS + 4*BQ) * (int)sizeof(float); // ~194 KB
    cudaFuncSetAttribute(proj_kernel, cudaFuncAttributeMaxDynamicSharedMemorySize, smem_proj);
    cudaFuncSetAttribute(attn_kernel, cudaFuncAttributeMaxDynamicSharedMemorySize, smem_attn);

    proj_kernel<<<dim3(NROWS/64, 3), 256, smem_proj>>>(emb, WQ, WK, WV);
    attn_kernel<<<dim3(32, B_), NT, smem_attn>>>(out);
}